// round 5
// baseline (speedup 1.0000x reference)
#include <cuda_runtime.h>

typedef unsigned long long u64;

// ---------------- device scratch ----------------
__device__ float g_Bmat[128 * 1024];     // [k'][ij]: k'<64 -> invSigma, k'>=64 -> -2*mu*invSigma
__device__ float g_Cc[1024];             // C[ij]
__device__ float g_KG[1024 * 128];       // [ij][c]: c<64 -> K, c>=64 -> v - K*mu
__device__ float g_W[1024 * 1024];       // weights
__device__ float g_part[8 * 1024 * 128]; // GEMM2 k-split partials
__device__ float g_denp[8 * 1024];       // den partials per GEMM1 n-block

// ---------------- packed f32x2 helpers ----------------
__device__ __forceinline__ u64 pack2(float lo, float hi) {
    u64 r; asm("mov.b64 %0,{%1,%2};" : "=l"(r) : "f"(lo), "f"(hi)); return r;
}
__device__ __forceinline__ void unpack2(u64 v, float& lo, float& hi) {
    asm("mov.b64 {%0,%1},%2;" : "=f"(lo), "=f"(hi) : "l"(v));
}
__device__ __forceinline__ void fma2(u64& c, u64 a, u64 b) {
    asm("fma.rn.f32x2 %0,%1,%2,%0;" : "+l"(c) : "l"(a), "l"(b));
}

// ---------------- kernel 1: precompute, warp per ij, smem-transposed Bmat ----------------
__global__ __launch_bounds__(1024) void precompute_ij(const float* __restrict__ Mu0,
                                                      const float* __restrict__ Mu1,
                                                      const float* __restrict__ S0,
                                                      const float* __restrict__ S1,
                                                      const float* __restrict__ tptr) {
    __shared__ float bm[128][33];   // [k'][local ij], padded
    const int tid = threadIdx.x;
    const int w = tid >> 5, lane = tid & 31;
    const int ij0 = blockIdx.x * 32;
    const int ij = ij0 + w;
    const int i = ij >> 5, j = ij & 31;
    const float t = *tptr, u = 1.0f - t;

    float Csum = 0.0f;
    #pragma unroll
    for (int kk = 0; kk < 2; kk++) {
        int k = kk * 32 + lane;
        float s0 = S0[i * 64 + k], s1 = S1[j * 64 + k];
        float m0 = Mu0[i * 64 + k], m1 = Mu1[j * 64 + k];
        float Ds = sqrtf(4.0f * s0 * s1 + 0.0625f);
        float Cs = 0.5f * (Ds - 0.25f);
        float mu = u * m0 + t * m1;
        float Sig = u * u * s0 + t * t * s1 + 2.0f * t * u * (Cs + 0.125f);
        float St = t * s1 + u * Cs - (u * s0 + t * Cs) - 0.25f * t;
        float invS = 1.0f / Sig;
        float Kv = St * invS;
        float v = m1 - m0;
        bm[k][w] = invS;
        bm[64 + k][w] = -2.0f * mu * invS;
        g_KG[ij * 128 + k] = Kv;
        g_KG[ij * 128 + 64 + k] = v - Kv * mu;
        Csum += mu * mu * invS + __logf(Sig);
    }
    #pragma unroll
    for (int o = 16; o > 0; o >>= 1) Csum += __shfl_xor_sync(0xffffffffu, Csum, o);
    if (lane == 0) g_Cc[ij] = Csum;
    __syncthreads();

    // coalesced writeout: thread t -> row r = t>>3, cols (t&7)*4 .. +3
    const int r = tid >> 3, c = (tid & 7) * 4;
    float4 v4 = make_float4(bm[r][c], bm[r][c + 1], bm[r][c + 2], bm[r][c + 3]);
    *(float4*)&g_Bmat[r * 1024 + ij0 + c] = v4;
}

// ================= GEMM geometry: BM=64, BN=128, BK=16, 256 threads =================
// thread tile 4m x 8n; acc f32x2 packed along m (2 pairs x 8).

// ---------------- GEMM1: q = Xext @ Bmat, W epilogue ----------------
__global__ __launch_bounds__(256) void gemm1_kernel(const float* __restrict__ X,
                                                    const float* __restrict__ Lam) {
    __shared__ float As[2][16][64];   // 8 KB
    __shared__ float Bs[2][16][128];  // 16 KB

    const int tid = threadIdx.x;
    const int tx = tid & 15, ty = tid >> 4;
    const int m0 = blockIdx.x * 64, n0 = blockIdx.y * 128;

    const int rA = tid & 63, sA = tid >> 6;       // A stage: row, k-seg(0..3)
    const int rB = tid >> 4, cB = (tid & 15) * 8; // B stage

    u64 acc[2][8];
    #pragma unroll
    for (int i = 0; i < 2; i++)
        #pragma unroll
        for (int j = 0; j < 8; j++) acc[i][j] = 0ULL;

    // stage chunk 0 (X cols 0..15, squared)
    {
        float4 v = *(const float4*)&X[(m0 + rA) * 64 + sA * 4];
        v.x *= v.x; v.y *= v.y; v.z *= v.z; v.w *= v.w;
        As[0][sA * 4 + 0][rA] = v.x; As[0][sA * 4 + 1][rA] = v.y;
        As[0][sA * 4 + 2][rA] = v.z; As[0][sA * 4 + 3][rA] = v.w;
        *(float4*)&Bs[0][rB][cB]     = *(const float4*)&g_Bmat[rB * 1024 + n0 + cB];
        *(float4*)&Bs[0][rB][cB + 4] = *(const float4*)&g_Bmat[rB * 1024 + n0 + cB + 4];
    }
    __syncthreads();

    #pragma unroll 1
    for (int c = 0; c < 8; c++) {
        const int p = c & 1;
        float4 va, vb0, vb1;
        if (c < 7) {
            int cc = c + 1;
            va = *(const float4*)&X[(m0 + rA) * 64 + (cc & 3) * 16 + sA * 4];
            if (cc < 4) { va.x *= va.x; va.y *= va.y; va.z *= va.z; va.w *= va.w; }
            vb0 = *(const float4*)&g_Bmat[(cc * 16 + rB) * 1024 + n0 + cB];
            vb1 = *(const float4*)&g_Bmat[(cc * 16 + rB) * 1024 + n0 + cB + 4];
        }
        #pragma unroll
        for (int k = 0; k < 16; k++) {
            ulonglong2 a = *(const ulonglong2*)&As[p][k][ty * 4];
            float4 b0 = *(const float4*)&Bs[p][k][tx * 8];
            float4 b1 = *(const float4*)&Bs[p][k][tx * 8 + 4];
            u64 bb[8] = {pack2(b0.x, b0.x), pack2(b0.y, b0.y), pack2(b0.z, b0.z), pack2(b0.w, b0.w),
                         pack2(b1.x, b1.x), pack2(b1.y, b1.y), pack2(b1.z, b1.z), pack2(b1.w, b1.w)};
            #pragma unroll
            for (int j = 0; j < 8; j++) {
                fma2(acc[0][j], a.x, bb[j]);
                fma2(acc[1][j], a.y, bb[j]);
            }
        }
        if (c < 7) {
            As[p ^ 1][sA * 4 + 0][rA] = va.x; As[p ^ 1][sA * 4 + 1][rA] = va.y;
            As[p ^ 1][sA * 4 + 2][rA] = va.z; As[p ^ 1][sA * 4 + 3][rA] = va.w;
            *(float4*)&Bs[p ^ 1][rB][cB]     = vb0;
            *(float4*)&Bs[p ^ 1][rB][cB + 4] = vb1;
            __syncthreads();
        }
    }

    // epilogue
    float cc8[8], ll8[8];
    *(float4*)&cc8[0] = *(const float4*)&g_Cc[n0 + tx * 8];
    *(float4*)&cc8[4] = *(const float4*)&g_Cc[n0 + tx * 8 + 4];
    *(float4*)&ll8[0] = *(const float4*)&Lam[n0 + tx * 8];
    *(float4*)&ll8[4] = *(const float4*)&Lam[n0 + tx * 8 + 4];

    #pragma unroll
    for (int mp = 0; mp < 2; mp++) {
        float wlo[8], whi[8];
        #pragma unroll
        for (int j = 0; j < 8; j++) {
            float qlo, qhi;
            unpack2(acc[mp][j], qlo, qhi);
            wlo[j] = __expf(fminf(fmaxf(-0.5f * (qlo + cc8[j]), -50.0f), 50.0f)) * ll8[j];
            whi[j] = __expf(fminf(fmaxf(-0.5f * (qhi + cc8[j]), -50.0f), 50.0f)) * ll8[j];
        }
        int mlo = m0 + ty * 4 + 2 * mp;
        *(float4*)&g_W[mlo * 1024 + n0 + tx * 8]           = *(float4*)&wlo[0];
        *(float4*)&g_W[mlo * 1024 + n0 + tx * 8 + 4]       = *(float4*)&wlo[4];
        *(float4*)&g_W[(mlo + 1) * 1024 + n0 + tx * 8]     = *(float4*)&whi[0];
        *(float4*)&g_W[(mlo + 1) * 1024 + n0 + tx * 8 + 4] = *(float4*)&whi[4];
        float rlo = ((wlo[0] + wlo[1]) + (wlo[2] + wlo[3])) + ((wlo[4] + wlo[5]) + (wlo[6] + wlo[7]));
        float rhi = ((whi[0] + whi[1]) + (whi[2] + whi[3])) + ((whi[4] + whi[5]) + (whi[6] + whi[7]));
        #pragma unroll
        for (int o = 1; o < 8; o <<= 1) {
            rlo += __shfl_xor_sync(0xffffffffu, rlo, o);
            rhi += __shfl_xor_sync(0xffffffffu, rhi, o);
        }
        rlo += __shfl_xor_sync(0xffffffffu, rlo, 8);
        rhi += __shfl_xor_sync(0xffffffffu, rhi, 8);
        if (tx == 0) {   // FIXED: one writer per 16-lane group; covers ALL rows
            g_denp[blockIdx.y * 1024 + mlo]     = rlo;
            g_denp[blockIdx.y * 1024 + mlo + 1] = rhi;
        }
    }
}

// ---------------- GEMM2: part = W @ KG, k-split 8 ----------------
__global__ __launch_bounds__(256) void gemm2_kernel() {
    __shared__ float As[2][16][64];
    __shared__ float Bs[2][16][128];

    const int tid = threadIdx.x;
    const int tx = tid & 15, ty = tid >> 4;
    const int m0 = blockIdx.x * 64;
    const int k0 = blockIdx.z * 128;

    const int rA = tid & 63, sA = tid >> 6;
    const int rB = tid >> 4, cB = (tid & 15) * 8;

    u64 acc[2][8];
    #pragma unroll
    for (int i = 0; i < 2; i++)
        #pragma unroll
        for (int j = 0; j < 8; j++) acc[i][j] = 0ULL;

    {
        float4 v = *(const float4*)&g_W[(m0 + rA) * 1024 + k0 + sA * 4];
        As[0][sA * 4 + 0][rA] = v.x; As[0][sA * 4 + 1][rA] = v.y;
        As[0][sA * 4 + 2][rA] = v.z; As[0][sA * 4 + 3][rA] = v.w;
        *(float4*)&Bs[0][rB][cB]     = *(const float4*)&g_KG[(k0 + rB) * 128 + cB];
        *(float4*)&Bs[0][rB][cB + 4] = *(const float4*)&g_KG[(k0 + rB) * 128 + cB + 4];
    }
    __syncthreads();

    #pragma unroll 1
    for (int c = 0; c < 8; c++) {
        const int p = c & 1;
        float4 va, vb0, vb1;
        if (c < 7) {
            int cc = c + 1;
            va  = *(const float4*)&g_W[(m0 + rA) * 1024 + k0 + cc * 16 + sA * 4];
            vb0 = *(const float4*)&g_KG[(k0 + cc * 16 + rB) * 128 + cB];
            vb1 = *(const float4*)&g_KG[(k0 + cc * 16 + rB) * 128 + cB + 4];
        }
        #pragma unroll
        for (int k = 0; k < 16; k++) {
            ulonglong2 a = *(const ulonglong2*)&As[p][k][ty * 4];
            float4 b0 = *(const float4*)&Bs[p][k][tx * 8];
            float4 b1 = *(const float4*)&Bs[p][k][tx * 8 + 4];
            u64 bb[8] = {pack2(b0.x, b0.x), pack2(b0.y, b0.y), pack2(b0.z, b0.z), pack2(b0.w, b0.w),
                         pack2(b1.x, b1.x), pack2(b1.y, b1.y), pack2(b1.z, b1.z), pack2(b1.w, b1.w)};
            #pragma unroll
            for (int j = 0; j < 8; j++) {
                fma2(acc[0][j], a.x, bb[j]);
                fma2(acc[1][j], a.y, bb[j]);
            }
        }
        if (c < 7) {
            As[p ^ 1][sA * 4 + 0][rA] = va.x; As[p ^ 1][sA * 4 + 1][rA] = va.y;
            As[p ^ 1][sA * 4 + 2][rA] = va.z; As[p ^ 1][sA * 4 + 3][rA] = va.w;
            *(float4*)&Bs[p ^ 1][rB][cB]     = vb0;
            *(float4*)&Bs[p ^ 1][rB][cB + 4] = vb1;
            __syncthreads();
        }
    }

    const int s = blockIdx.z;
    #pragma unroll
    for (int mp = 0; mp < 2; mp++) {
        float vlo[8], vhi[8];
        #pragma unroll
        for (int j = 0; j < 8; j++) unpack2(acc[mp][j], vlo[j], vhi[j]);
        int mlo = m0 + ty * 4 + 2 * mp;
        *(float4*)&g_part[(s * 1024 + mlo) * 128 + tx * 8]         = *(float4*)&vlo[0];
        *(float4*)&g_part[(s * 1024 + mlo) * 128 + tx * 8 + 4]     = *(float4*)&vlo[4];
        *(float4*)&g_part[(s * 1024 + mlo + 1) * 128 + tx * 8]     = *(float4*)&vhi[0];
        *(float4*)&g_part[(s * 1024 + mlo + 1) * 128 + tx * 8 + 4] = *(float4*)&vhi[4];
    }
}

// ---------------- final: 64 blocks x 256 threads, float4 loads ----------------
__global__ __launch_bounds__(256) void final_kernel(const float* __restrict__ X,
                                                    float* __restrict__ out) {
    const int tid = threadIdx.x;
    const int rb = tid >> 4;            // row in block (0..15)
    const int l = tid & 15;             // 16 lanes per row, 4 k's each
    const int b = blockIdx.x * 16 + rb;
    const int k4 = l * 4;

    float4 A = make_float4(0.f, 0.f, 0.f, 0.f);
    float4 Bv = make_float4(0.f, 0.f, 0.f, 0.f);
    #pragma unroll
    for (int s = 0; s < 8; s++) {
        float4 a = *(const float4*)&g_part[(s * 1024 + b) * 128 + k4];
        float4 q = *(const float4*)&g_part[(s * 1024 + b) * 128 + 64 + k4];
        A.x += a.x; A.y += a.y; A.z += a.z; A.w += a.w;
        Bv.x += q.x; Bv.y += q.y; Bv.z += q.z; Bv.w += q.w;
    }
    float d = (l < 8) ? g_denp[l * 1024 + b] : 0.0f;
    #pragma unroll
    for (int o = 1; o < 16; o <<= 1) d += __shfl_xor_sync(0xffffffffu, d, o);
    float inv = 1.0f / d;
    float4 x = *(const float4*)&X[b * 64 + k4];
    float4 o4;
    o4.x = (x.x * A.x + Bv.x) * inv;
    o4.y = (x.y * A.y + Bv.y) * inv;
    o4.z = (x.z * A.z + Bv.z) * inv;
    o4.w = (x.w * A.w + Bv.w) * inv;
    *(float4*)&out[b * 64 + k4] = o4;
}

// ---------------- launch ----------------
extern "C" void kernel_launch(void* const* d_in, const int* in_sizes, int n_in,
                              void* d_out, int out_size) {
    const float* X   = (const float*)d_in[0];
    const float* Mu0 = (const float*)d_in[1];
    const float* Mu1 = (const float*)d_in[2];
    const float* S0  = (const float*)d_in[3];
    const float* S1  = (const float*)d_in[4];
    const float* Lam = (const float*)d_in[5];
    const float* t   = (const float*)d_in[6];
    float* out = (float*)d_out;

    precompute_ij<<<32, 1024>>>(Mu0, Mu1, S0, S1, t);
    gemm1_kernel<<<dim3(16, 8), 256>>>(X, Lam);
    gemm2_kernel<<<dim3(16, 1, 8), 256>>>();
    final_kernel<<<64, 256>>>(X, out);
}

// round 6
// speedup vs baseline: 1.2718x; 1.2718x over previous
#include <cuda_runtime.h>

typedef unsigned long long u64;

// ---------------- device scratch ----------------
__device__ float g_Bmat[128 * 1024];     // [k'][ij]
__device__ float g_Cc[1024];             // C[ij]
__device__ float g_KG[1024 * 128];       // [ij][c]
__device__ float g_W[1024 * 1024];       // weights
__device__ float g_part[8 * 1024 * 128]; // GEMM2 k-split partials
__device__ float g_denp[16 * 1024];      // den partials per GEMM1 n-block (16 n-blocks)

// ---------------- packed f32x2 helpers ----------------
__device__ __forceinline__ u64 pack2(float lo, float hi) {
    u64 r; asm("mov.b64 %0,{%1,%2};" : "=l"(r) : "f"(lo), "f"(hi)); return r;
}
__device__ __forceinline__ void unpack2(u64 v, float& lo, float& hi) {
    asm("mov.b64 {%0,%1},%2;" : "=f"(lo), "=f"(hi) : "l"(v));
}
__device__ __forceinline__ void fma2(u64& c, u64 a, u64 b) {
    asm("fma.rn.f32x2 %0,%1,%2,%0;" : "+l"(c) : "l"(a), "l"(b));
}

// ---------------- kernel 1: precompute (unchanged from R5) ----------------
__global__ __launch_bounds__(1024) void precompute_ij(const float* __restrict__ Mu0,
                                                      const float* __restrict__ Mu1,
                                                      const float* __restrict__ S0,
                                                      const float* __restrict__ S1,
                                                      const float* __restrict__ tptr) {
    __shared__ float bm[128][33];
    const int tid = threadIdx.x;
    const int w = tid >> 5, lane = tid & 31;
    const int ij0 = blockIdx.x * 32;
    const int ij = ij0 + w;
    const int i = ij >> 5, j = ij & 31;
    const float t = *tptr, u = 1.0f - t;

    float Csum = 0.0f;
    #pragma unroll
    for (int kk = 0; kk < 2; kk++) {
        int k = kk * 32 + lane;
        float s0 = S0[i * 64 + k], s1 = S1[j * 64 + k];
        float m0 = Mu0[i * 64 + k], m1 = Mu1[j * 64 + k];
        float Ds = sqrtf(4.0f * s0 * s1 + 0.0625f);
        float Cs = 0.5f * (Ds - 0.25f);
        float mu = u * m0 + t * m1;
        float Sig = u * u * s0 + t * t * s1 + 2.0f * t * u * (Cs + 0.125f);
        float St = t * s1 + u * Cs - (u * s0 + t * Cs) - 0.25f * t;
        float invS = 1.0f / Sig;
        float Kv = St * invS;
        float v = m1 - m0;
        bm[k][w] = invS;
        bm[64 + k][w] = -2.0f * mu * invS;
        g_KG[ij * 128 + k] = Kv;
        g_KG[ij * 128 + 64 + k] = v - Kv * mu;
        Csum += mu * mu * invS + __logf(Sig);
    }
    #pragma unroll
    for (int o = 16; o > 0; o >>= 1) Csum += __shfl_xor_sync(0xffffffffu, Csum, o);
    if (lane == 0) g_Cc[ij] = Csum;
    __syncthreads();

    const int r = tid >> 3, c = (tid & 7) * 4;
    float4 v4 = make_float4(bm[r][c], bm[r][c + 1], bm[r][c + 2], bm[r][c + 3]);
    *(float4*)&g_Bmat[r * 1024 + ij0 + c] = v4;
}

// ================= GEMM geometry: BM=64, BN=64, BK=16, 256 threads =================
// thread tile 4m x 4n; acc f32x2 packed along m (2 pairs x 4 n).

// ---------------- GEMM1: q = Xext @ Bmat, W epilogue ----------------
__global__ __launch_bounds__(256) void gemm1_kernel(const float* __restrict__ X,
                                                    const float* __restrict__ Lam) {
    __shared__ float As[2][16][64];   // 8 KB
    __shared__ float Bs[2][16][64];   // 8 KB

    const int tid = threadIdx.x;
    const int tx = tid & 15, ty = tid >> 4;
    const int m0 = blockIdx.x * 64, n0 = blockIdx.y * 64;

    const int rA = tid & 63, sA = tid >> 6;       // A stage: row, k-seg(0..3)
    const int rB = tid >> 4, cB = (tid & 15) * 4; // B stage

    u64 acc[2][4];
    #pragma unroll
    for (int i = 0; i < 2; i++)
        #pragma unroll
        for (int j = 0; j < 4; j++) acc[i][j] = 0ULL;

    // stage chunk 0 (X cols 0..15, squared)
    {
        float4 v = *(const float4*)&X[(m0 + rA) * 64 + sA * 4];
        v.x *= v.x; v.y *= v.y; v.z *= v.z; v.w *= v.w;
        As[0][sA * 4 + 0][rA] = v.x; As[0][sA * 4 + 1][rA] = v.y;
        As[0][sA * 4 + 2][rA] = v.z; As[0][sA * 4 + 3][rA] = v.w;
        *(float4*)&Bs[0][rB][cB] = *(const float4*)&g_Bmat[rB * 1024 + n0 + cB];
    }
    __syncthreads();

    #pragma unroll 1
    for (int c = 0; c < 8; c++) {
        const int p = c & 1;
        float4 va, vb;
        if (c < 7) {
            int cc = c + 1;
            va = *(const float4*)&X[(m0 + rA) * 64 + (cc & 3) * 16 + sA * 4];
            if (cc < 4) { va.x *= va.x; va.y *= va.y; va.z *= va.z; va.w *= va.w; }
            vb = *(const float4*)&g_Bmat[(cc * 16 + rB) * 1024 + n0 + cB];
        }
        #pragma unroll
        for (int k = 0; k < 16; k++) {
            ulonglong2 a = *(const ulonglong2*)&As[p][k][ty * 4];
            float4 b = *(const float4*)&Bs[p][k][tx * 4];
            u64 b0 = pack2(b.x, b.x), b1 = pack2(b.y, b.y);
            u64 b2 = pack2(b.z, b.z), b3 = pack2(b.w, b.w);
            fma2(acc[0][0], a.x, b0); fma2(acc[1][0], a.y, b0);
            fma2(acc[0][1], a.x, b1); fma2(acc[1][1], a.y, b1);
            fma2(acc[0][2], a.x, b2); fma2(acc[1][2], a.y, b2);
            fma2(acc[0][3], a.x, b3); fma2(acc[1][3], a.y, b3);
        }
        if (c < 7) {
            As[p ^ 1][sA * 4 + 0][rA] = va.x; As[p ^ 1][sA * 4 + 1][rA] = va.y;
            As[p ^ 1][sA * 4 + 2][rA] = va.z; As[p ^ 1][sA * 4 + 3][rA] = va.w;
            *(float4*)&Bs[p ^ 1][rB][cB] = vb;
            __syncthreads();
        }
    }

    // epilogue
    float4 cc4 = *(const float4*)&g_Cc[n0 + tx * 4];
    float4 ll4 = *(const float4*)&Lam[n0 + tx * 4];
    float ccs[4] = {cc4.x, cc4.y, cc4.z, cc4.w};
    float lls[4] = {ll4.x, ll4.y, ll4.z, ll4.w};

    #pragma unroll
    for (int mp = 0; mp < 2; mp++) {
        float wlo[4], whi[4];
        #pragma unroll
        for (int j = 0; j < 4; j++) {
            float qlo, qhi;
            unpack2(acc[mp][j], qlo, qhi);
            wlo[j] = __expf(fminf(fmaxf(-0.5f * (qlo + ccs[j]), -50.0f), 50.0f)) * lls[j];
            whi[j] = __expf(fminf(fmaxf(-0.5f * (qhi + ccs[j]), -50.0f), 50.0f)) * lls[j];
        }
        int mlo = m0 + ty * 4 + 2 * mp;
        *(float4*)&g_W[mlo * 1024 + n0 + tx * 4]       = *(float4*)&wlo[0];
        *(float4*)&g_W[(mlo + 1) * 1024 + n0 + tx * 4] = *(float4*)&whi[0];
        float rlo = (wlo[0] + wlo[1]) + (wlo[2] + wlo[3]);
        float rhi = (whi[0] + whi[1]) + (whi[2] + whi[3]);
        #pragma unroll
        for (int o = 1; o < 16; o <<= 1) {
            rlo += __shfl_xor_sync(0xffffffffu, rlo, o);
            rhi += __shfl_xor_sync(0xffffffffu, rhi, o);
        }
        if (tx == 0) {
            g_denp[blockIdx.y * 1024 + mlo]     = rlo;
            g_denp[blockIdx.y * 1024 + mlo + 1] = rhi;
        }
    }
}

// ---------------- GEMM2: part = W @ KG, k-split 8 ----------------
__global__ __launch_bounds__(256) void gemm2_kernel() {
    __shared__ float As[2][16][64];
    __shared__ float Bs[2][16][64];

    const int tid = threadIdx.x;
    const int tx = tid & 15, ty = tid >> 4;
    const int m0 = blockIdx.x * 64, n0 = blockIdx.y * 64;
    const int k0 = blockIdx.z * 128;

    const int rA = tid & 63, sA = tid >> 6;
    const int rB = tid >> 4, cB = (tid & 15) * 4;

    u64 acc[2][4];
    #pragma unroll
    for (int i = 0; i < 2; i++)
        #pragma unroll
        for (int j = 0; j < 4; j++) acc[i][j] = 0ULL;

    {
        float4 v = *(const float4*)&g_W[(m0 + rA) * 1024 + k0 + sA * 4];
        As[0][sA * 4 + 0][rA] = v.x; As[0][sA * 4 + 1][rA] = v.y;
        As[0][sA * 4 + 2][rA] = v.z; As[0][sA * 4 + 3][rA] = v.w;
        *(float4*)&Bs[0][rB][cB] = *(const float4*)&g_KG[(k0 + rB) * 128 + n0 + cB];
    }
    __syncthreads();

    #pragma unroll 1
    for (int c = 0; c < 8; c++) {
        const int p = c & 1;
        float4 va, vb;
        if (c < 7) {
            int cc = c + 1;
            va = *(const float4*)&g_W[(m0 + rA) * 1024 + k0 + cc * 16 + sA * 4];
            vb = *(const float4*)&g_KG[(k0 + cc * 16 + rB) * 128 + n0 + cB];
        }
        #pragma unroll
        for (int k = 0; k < 16; k++) {
            ulonglong2 a = *(const ulonglong2*)&As[p][k][ty * 4];
            float4 b = *(const float4*)&Bs[p][k][tx * 4];
            u64 b0 = pack2(b.x, b.x), b1 = pack2(b.y, b.y);
            u64 b2 = pack2(b.z, b.z), b3 = pack2(b.w, b.w);
            fma2(acc[0][0], a.x, b0); fma2(acc[1][0], a.y, b0);
            fma2(acc[0][1], a.x, b1); fma2(acc[1][1], a.y, b1);
            fma2(acc[0][2], a.x, b2); fma2(acc[1][2], a.y, b2);
            fma2(acc[0][3], a.x, b3); fma2(acc[1][3], a.y, b3);
        }
        if (c < 7) {
            As[p ^ 1][sA * 4 + 0][rA] = va.x; As[p ^ 1][sA * 4 + 1][rA] = va.y;
            As[p ^ 1][sA * 4 + 2][rA] = va.z; As[p ^ 1][sA * 4 + 3][rA] = va.w;
            *(float4*)&Bs[p ^ 1][rB][cB] = vb;
            __syncthreads();
        }
    }

    const int s = blockIdx.z;
    #pragma unroll
    for (int mp = 0; mp < 2; mp++) {
        float vlo[4], vhi[4];
        #pragma unroll
        for (int j = 0; j < 4; j++) unpack2(acc[mp][j], vlo[j], vhi[j]);
        int mlo = m0 + ty * 4 + 2 * mp;
        *(float4*)&g_part[(s * 1024 + mlo) * 128 + n0 + tx * 4]       = *(float4*)&vlo[0];
        *(float4*)&g_part[(s * 1024 + mlo + 1) * 128 + n0 + tx * 4]   = *(float4*)&vhi[0];
    }
}

// ---------------- final: warp per batch row, 256 blocks ----------------
__global__ __launch_bounds__(128) void final_kernel(const float* __restrict__ X,
                                                    float* __restrict__ out) {
    const int tid = threadIdx.x;
    const int b = blockIdx.x * 4 + (tid >> 5);   // warp per row
    const int lane = tid & 31;
    const int l = lane & 15;                      // n-col group (4 cols)
    const int h = lane >> 4;                      // split half: s in [h*4, h*4+4)
    const int k4 = l * 4;

    float4 A = make_float4(0.f, 0.f, 0.f, 0.f);
    float4 Bv = make_float4(0.f, 0.f, 0.f, 0.f);
    #pragma unroll
    for (int si = 0; si < 4; si++) {
        int s = h * 4 + si;
        float4 a = *(const float4*)&g_part[(s * 1024 + b) * 128 + k4];
        float4 q = *(const float4*)&g_part[(s * 1024 + b) * 128 + 64 + k4];
        A.x += a.x; A.y += a.y; A.z += a.z; A.w += a.w;
        Bv.x += q.x; Bv.y += q.y; Bv.z += q.z; Bv.w += q.w;
    }
    // combine split halves across xor-16 partner
    A.x += __shfl_xor_sync(0xffffffffu, A.x, 16);
    A.y += __shfl_xor_sync(0xffffffffu, A.y, 16);
    A.z += __shfl_xor_sync(0xffffffffu, A.z, 16);
    A.w += __shfl_xor_sync(0xffffffffu, A.w, 16);
    Bv.x += __shfl_xor_sync(0xffffffffu, Bv.x, 16);
    Bv.y += __shfl_xor_sync(0xffffffffu, Bv.y, 16);
    Bv.z += __shfl_xor_sync(0xffffffffu, Bv.z, 16);
    Bv.w += __shfl_xor_sync(0xffffffffu, Bv.w, 16);

    // den: 16 partials, every lane loads (lane&15)-th, reduce within 16-group
    float d = g_denp[l * 1024 + b];
    #pragma unroll
    for (int o = 1; o < 16; o <<= 1) d += __shfl_xor_sync(0xffffffffu, d, o);
    float inv = 1.0f / d;

    if (h == 0) {
        float4 x = *(const float4*)&X[b * 64 + k4];
        float4 o4;
        o4.x = (x.x * A.x + Bv.x) * inv;
        o4.y = (x.y * A.y + Bv.y) * inv;
        o4.z = (x.z * A.z + Bv.z) * inv;
        o4.w = (x.w * A.w + Bv.w) * inv;
        *(float4*)&out[b * 64 + k4] = o4;
    }
}

// ---------------- launch ----------------
extern "C" void kernel_launch(void* const* d_in, const int* in_sizes, int n_in,
                              void* d_out, int out_size) {
    const float* X   = (const float*)d_in[0];
    const float* Mu0 = (const float*)d_in[1];
    const float* Mu1 = (const float*)d_in[2];
    const float* S0  = (const float*)d_in[3];
    const float* S1  = (const float*)d_in[4];
    const float* Lam = (const float*)d_in[5];
    const float* t   = (const float*)d_in[6];
    float* out = (float*)d_out;

    precompute_ij<<<32, 1024>>>(Mu0, Mu1, S0, S1, t);
    gemm1_kernel<<<dim3(16, 16), 256>>>(X, Lam);
    gemm2_kernel<<<dim3(16, 2, 8), 256>>>();
    final_kernel<<<256, 128>>>(X, out);
}